// round 5
// baseline (speedup 1.0000x reference)
#include <cuda_runtime.h>
#include <cuda_bf16.h>
#include <cstdint>

// ---------------- problem constants ----------------
#define N_NODES   65536
#define N_EDGES   1048576
#define KCODES    8192
#define DIM       512

#define OFF_ZQ    0
#define OFF_LOSS  33554432
#define OFF_IDX   33554433
#define OFF_EDGE  33619969

// ---------------- scratch (static device globals; no runtime alloc) ----------
__device__ __nv_bfloat16 g_xh[(size_t)N_NODES * DIM];
__device__ __nv_bfloat16 g_xl[(size_t)N_NODES * DIM];
__device__ __nv_bfloat16 g_eh[(size_t)KCODES * DIM];
__device__ __nv_bfloat16 g_el[(size_t)KCODES * DIM];
__device__ float              g_xnorm[N_NODES];
__device__ unsigned long long g_best[N_NODES];
__device__ float              g_rowsq[N_NODES];
__device__ float              g_partial[256];
__device__ int                g_edge_is64;

// ---------------- helpers ----------------
__device__ __forceinline__ uint32_t smem_u32(const void* p) {
    uint32_t a;
    asm("{ .reg .u64 t; cvta.to.shared.u64 t, %1; cvt.u32.u64 %0, t; }" : "=r"(a) : "l"(p));
    return a;
}
#define SW128(off) ((off) ^ (((off) >> 3) & 0x70))

__device__ __forceinline__ void cp16(uint32_t dst, const void* src) {
    asm volatile("cp.async.cg.shared.global [%0], [%1], 16;" :: "r"(dst), "l"(src) : "memory");
}
__device__ __forceinline__ void cp_commit() { asm volatile("cp.async.commit_group;" ::: "memory"); }
template <int N> __device__ __forceinline__ void cp_wait() {
    asm volatile("cp.async.wait_group %0;" :: "n"(N) : "memory");
}
__device__ __forceinline__ void ldsm4(uint32_t& r0, uint32_t& r1, uint32_t& r2, uint32_t& r3,
                                      uint32_t addr) {
    asm volatile("ldmatrix.sync.aligned.m8n8.x4.shared.b16 {%0,%1,%2,%3}, [%4];"
                 : "=r"(r0), "=r"(r1), "=r"(r2), "=r"(r3) : "r"(addr));
}
__device__ __forceinline__ void mma16816(float* d, const uint32_t* a, uint32_t b0, uint32_t b1) {
    asm volatile(
        "mma.sync.aligned.m16n8k16.row.col.f32.bf16.bf16.f32 "
        "{%0,%1,%2,%3},{%4,%5,%6,%7},{%8,%9},{%0,%1,%2,%3};"
        : "+f"(d[0]), "+f"(d[1]), "+f"(d[2]), "+f"(d[3])
        : "r"(a[0]), "r"(a[1]), "r"(a[2]), "r"(a[3]), "r"(b0), "r"(b1));
}
__device__ __forceinline__ unsigned f2ord(float f) {
    unsigned u = __float_as_uint(f);
    return (u & 0x80000000u) ? ~u : (u | 0x80000000u);
}
__device__ __forceinline__ unsigned long long umin64(unsigned long long a, unsigned long long b) {
    return a < b ? a : b;
}
__device__ __forceinline__ void split_bf16(float v, __nv_bfloat16& h, __nv_bfloat16& l) {
    h = __float2bfloat16_rn(v);
    l = __float2bfloat16_rn(v - __bfloat162float(h));
}

// ---------------- prep kernels ----------------
// One warp per row; XLA-GPU row-reduce order for the norm:
// lane t accumulates x[t+32j]^2 for j=0..15 sequentially (square rounded
// separately from the add), then shfl.down tree 16/8/4/2/1.
__global__ void prep_x_kernel(const float* __restrict__ x) {
    int wid = threadIdx.x >> 5;
    int lane = threadIdx.x & 31;
    int row = blockIdx.x * 8 + wid;
    const float* xr = x + (size_t)row * DIM;
    float s = 0.f;
#pragma unroll
    for (int j = 0; j < 16; j++) {
        int idx = lane + 32 * j;
        float v = xr[idx];
        s = __fadd_rn(s, __fmul_rn(v, v));          // fl(s + fl(v*v)), in order
        __nv_bfloat16 h, l;
        split_bf16(v, h, l);
        g_xh[(size_t)row * DIM + idx] = h;
        g_xl[(size_t)row * DIM + idx] = l;
    }
#pragma unroll
    for (int o = 16; o > 0; o >>= 1)
        s = __fadd_rn(s, __shfl_down_sync(0xFFFFFFFFu, s, o));
    if (lane == 0) g_xnorm[row] = s;
}

__global__ void prep_e_kernel(const float* __restrict__ emb) {
    int k = blockIdx.x;             // 8192 blocks x 128 threads
    int t = threadIdx.x;
    float4 v = ((const float4*)(emb + (size_t)k * DIM))[t];
    __nv_bfloat16 h0, h1, h2, h3, l0, l1, l2, l3;
    split_bf16(v.x, h0, l0); split_bf16(v.y, h1, l1);
    split_bf16(v.z, h2, l2); split_bf16(v.w, h3, l3);
    ((ushort4*)g_eh)[(size_t)k * (DIM / 4) + t] =
        make_ushort4(__bfloat16_as_ushort(h0), __bfloat16_as_ushort(h1),
                     __bfloat16_as_ushort(h2), __bfloat16_as_ushort(h3));
    ((ushort4*)g_el)[(size_t)k * (DIM / 4) + t] =
        make_ushort4(__bfloat16_as_ushort(l0), __bfloat16_as_ushort(l1),
                     __bfloat16_as_ushort(l2), __bfloat16_as_ushort(l3));
}

__global__ void init_best_kernel() {
    int i = blockIdx.x * blockDim.x + threadIdx.x;
    if (i < N_NODES) g_best[i] = 0xFFFFFFFFFFFFFFFFull;
}

// Detect whether edge_index arrived as raw int64 (odd 32-bit words all zero;
// node ids < 65536 so int64 upper words are 0, while int32 odd slots are
// independent nonzero values w.h.p.).
__global__ void detect_edge_kernel(const int* __restrict__ e) {
    __shared__ int any;
    if (threadIdx.x == 0) any = 0;
    __syncthreads();
    if (e[2 * threadIdx.x + 1] != 0) any = 1;
    __syncthreads();
    if (threadIdx.x == 0) g_edge_is64 = (any == 0) ? 1 : 0;
}

__global__ void edge_out_kernel(const int* __restrict__ e, float* __restrict__ out, int out_size) {
    int is64 = g_edge_is64;
    for (int i = blockIdx.x * blockDim.x + threadIdx.x; i < 2 * N_EDGES;
         i += gridDim.x * blockDim.x) {
        int o = OFF_EDGE + i;
        if (o < out_size) {
            float v = is64 ? (float)((const long long*)e)[i] : (float)e[i];
            out[o] = v;
        }
    }
}

// ---------------- main GEMM + argmin kernel (mma.sync bf16, split hi/lo) ----
#define BM 128
#define BN 128
#define BK 64
#define NCHUNK (DIM / BK)        // 8
#define T_XH 0
#define T_XL 16384
#define T_EH 32768
#define T_EL 49152
#define STAGE_BYTES 65536
#define SMEM_DYN (2 * STAGE_BYTES)   // 131072

__device__ __forceinline__ void load_chunk(uint32_t sb, int s, int kc,
                                           int m_base, int n_base, int tid) {
    uint32_t stg = sb + s * STAGE_BYTES;
#pragma unroll
    for (int t = 0; t < 16; t++) {
        int id = tid + t * 256;          // 0..4095
        int tile = id >> 10;             // 0..3 : xh, xl, eh, el
        int idx = id & 1023;
        int r = idx >> 3;
        int seg = idx & 7;
        const __nv_bfloat16* gsrc =
            (tile == 0) ? g_xh : (tile == 1) ? g_xl : (tile == 2) ? g_eh : g_el;
        int row = ((tile < 2) ? m_base : n_base) + r;
        const char* src = (const char*)gsrc + ((size_t)row * (DIM * 2) + kc * (BK * 2) + seg * 16);
        uint32_t off = (uint32_t)(r * 128 + seg * 16);
        uint32_t dst = stg + tile * 16384 + SW128(off);
        cp16(dst, src);
    }
    cp_commit();
}

__global__ void __launch_bounds__(256) vq_gemm_kernel() {
    extern __shared__ char smem[];
    uint32_t sb = smem_u32(smem);
    int tid = threadIdx.x;
    int lane = tid & 31;
    int wid = tid >> 5;
    int warp_m = wid >> 1;           // 0..3  -> 32-row band
    int warp_n = wid & 1;            // 0..1  -> 64-col band
    int m_base = blockIdx.y * BM;
    int n_base = blockIdx.x * BN;

    float acc[2][8][4];
#pragma unroll
    for (int a = 0; a < 2; a++)
#pragma unroll
        for (int b = 0; b < 8; b++)
#pragma unroll
            for (int c = 0; c < 4; c++) acc[a][b][c] = 0.f;

    load_chunk(sb, 0, 0, m_base, n_base, tid);
    load_chunk(sb, 1, 1, m_base, n_base, tid);

#pragma unroll 1
    for (int i = 0; i < NCHUNK; i++) {
        int s = i & 1;
        if (i < NCHUNK - 1) cp_wait<1>(); else cp_wait<0>();
        __syncthreads();
        uint32_t stg = sb + s * STAGE_BYTES;
#pragma unroll
        for (int kk = 0; kk < 4; kk++) {
            uint32_t axh[2][4], axl[2][4];
#pragma unroll
            for (int mt = 0; mt < 2; mt++) {
                uint32_t rowA = warp_m * 32 + mt * 16 + (lane & 15);
                uint32_t offA = SW128(rowA * 128 + kk * 32 + ((lane >> 4) << 4));
                ldsm4(axh[mt][0], axh[mt][1], axh[mt][2], axh[mt][3], stg + T_XH + offA);
                ldsm4(axl[mt][0], axl[mt][1], axl[mt][2], axl[mt][3], stg + T_XL + offA);
            }
            uint32_t bb[8][2];
#pragma unroll
            for (int jp = 0; jp < 4; jp++) {
                uint32_t rowB = warp_n * 64 + jp * 16 + (lane & 7) + ((lane >> 4) << 3);
                uint32_t offB = SW128(rowB * 128 + kk * 32 + (((lane >> 3) & 1) << 4));
                ldsm4(bb[2 * jp][0], bb[2 * jp][1], bb[2 * jp + 1][0], bb[2 * jp + 1][1],
                      stg + T_EH + offB);
            }
#pragma unroll
            for (int mt = 0; mt < 2; mt++)
#pragma unroll
                for (int j = 0; j < 8; j++) mma16816(acc[mt][j], axh[mt], bb[j][0], bb[j][1]);
#pragma unroll
            for (int mt = 0; mt < 2; mt++)
#pragma unroll
                for (int j = 0; j < 8; j++) mma16816(acc[mt][j], axl[mt], bb[j][0], bb[j][1]);
            // reload B as el, reuse axh
#pragma unroll
            for (int jp = 0; jp < 4; jp++) {
                uint32_t rowB = warp_n * 64 + jp * 16 + (lane & 7) + ((lane >> 4) << 3);
                uint32_t offB = SW128(rowB * 128 + kk * 32 + (((lane >> 3) & 1) << 4));
                ldsm4(bb[2 * jp][0], bb[2 * jp][1], bb[2 * jp + 1][0], bb[2 * jp + 1][1],
                      stg + T_EL + offB);
            }
#pragma unroll
            for (int mt = 0; mt < 2; mt++)
#pragma unroll
                for (int j = 0; j < 8; j++) mma16816(acc[mt][j], axh[mt], bb[j][0], bb[j][1]);
        }
        if (i + 2 < NCHUNK) {
            __syncthreads();
            load_chunk(sb, s, i + 2, m_base, n_base, tid);
        }
    }

    // ---- epilogue: d = fl(a - 2c) exactly as the reference rounds it ----
    // (||e_k||^2 < ULP(a)/2 always, so the reference's fl(a + b) == a: b drops out)
    int g = lane >> 2;
#pragma unroll
    for (int rr = 0; rr < 4; rr++) {
        int mt = rr >> 1, p = rr & 1;
        int row = m_base + warp_m * 32 + mt * 16 + p * 8 + g;
        float a = g_xnorm[row];
        unsigned long long best = 0xFFFFFFFFFFFFFFFFull;
#pragma unroll
        for (int j = 0; j < 8; j++) {
#pragma unroll
            for (int q = 0; q < 2; q++) {
                float c = acc[mt][j][p * 2 + q];
                float d = __fadd_rn(a, __fmul_rn(-2.0f, c));
                int col = n_base + warp_n * 64 + j * 8 + (lane & 3) * 2 + q;
                unsigned long long pk =
                    ((unsigned long long)f2ord(d) << 32) | (unsigned)col;
                best = umin64(best, pk);
            }
        }
        best = umin64(best, __shfl_xor_sync(0xFFFFFFFFu, best, 1));
        best = umin64(best, __shfl_xor_sync(0xFFFFFFFFu, best, 2));
        if ((lane & 3) == 0) atomicMin(&g_best[row], best);
    }
}

// ---------------- finalize: z_q gather (straight-through rounding), idx, sq --
__global__ void finalize_kernel(const float* __restrict__ x, const float* __restrict__ emb,
                                float* __restrict__ out, int out_size) {
    int row = blockIdx.x;           // 65536 blocks x 128 threads
    int t = threadIdx.x;
    int k = (int)(unsigned)(g_best[row] & 0xFFFFFFFFu);
    float4 ev = ((const float4*)(emb + (size_t)k * DIM))[t];
    float4 xv = ((const float4*)(x + (size_t)row * DIM))[t];
    // reference: z_q = fl(x + fl(e - x))  (double rounding, NOT exactly e)
    float4 dv;
    dv.x = __fadd_rn(ev.x, -xv.x);
    dv.y = __fadd_rn(ev.y, -xv.y);
    dv.z = __fadd_rn(ev.z, -xv.z);
    dv.w = __fadd_rn(ev.w, -xv.w);
    float4 zq;
    zq.x = __fadd_rn(xv.x, dv.x);
    zq.y = __fadd_rn(xv.y, dv.y);
    zq.z = __fadd_rn(xv.z, dv.z);
    zq.w = __fadd_rn(xv.w, dv.w);
    ((float4*)(out + OFF_ZQ))[(size_t)row * (DIM / 4) + t] = zq;
    float s = dv.x * dv.x + dv.y * dv.y + dv.z * dv.z + dv.w * dv.w;
    for (int o = 16; o > 0; o >>= 1) s += __shfl_down_sync(0xFFFFFFFFu, s, o);
    __shared__ float ws[4];
    if ((t & 31) == 0) ws[t >> 5] = s;
    __syncthreads();
    if (t == 0) {
        g_rowsq[row] = ws[0] + ws[1] + ws[2] + ws[3];
        int o = OFF_IDX + row;
        if (o < out_size) out[o] = (float)k;
    }
}

__global__ void loss_partial_kernel() {   // 256 blocks x 32 threads
    int b = blockIdx.x, t = threadIdx.x;
    float s = 0.f;
    for (int j = t; j < 256; j += 32) s += g_rowsq[b * 256 + j];
    for (int o = 16; o > 0; o >>= 1) s += __shfl_down_sync(0xFFFFFFFFu, s, o);
    if (t == 0) g_partial[b] = s;
}
__global__ void loss_final_kernel(float* __restrict__ out, int out_size) {
    if (threadIdx.x == 0 && blockIdx.x == 0) {
        float tot = 0.f;
        for (int i = 0; i < 256; i++) tot += g_partial[i];
        float loss = 1.25f * tot / (float)((size_t)N_NODES * DIM);
        if (OFF_LOSS < out_size) out[OFF_LOSS] = loss;
    }
}

// ---------------- launch ----------------
extern "C" void kernel_launch(void* const* d_in, const int* in_sizes, int n_in,
                              void* d_out, int out_size) {
    // Positional binding per metadata order: x, edge_index, emb.
    const float* x    = (const float*)d_in[0];
    const int*   eidx = (n_in > 1) ? (const int*)d_in[1] : nullptr;
    const float* emb  = (n_in > 2) ? (const float*)d_in[2] : (const float*)d_in[n_in - 1];
    // Sanity fallback: if sizes clearly identify tensors, prefer that.
    for (int i = 0; i < n_in; i++) {
        if (in_sizes[i] == N_NODES * DIM) x = (const float*)d_in[i];
        if (in_sizes[i] == KCODES * DIM && i != 0) emb = (const float*)d_in[i];
    }
    float* out = (float*)d_out;

    prep_x_kernel<<<N_NODES / 8, 256>>>(x);
    prep_e_kernel<<<KCODES, 128>>>(emb);
    init_best_kernel<<<N_NODES / 256, 256>>>();
    if (eidx) {
        detect_edge_kernel<<<1, 256>>>(eidx);
        edge_out_kernel<<<2048, 256>>>(eidx, out, out_size);
    }

    cudaFuncSetAttribute(vq_gemm_kernel, cudaFuncAttributeMaxDynamicSharedMemorySize, SMEM_DYN);
    dim3 grid(KCODES / BN, N_NODES / BM);   // (64, 512)
    vq_gemm_kernel<<<grid, 256, SMEM_DYN>>>();

    finalize_kernel<<<N_NODES, 128>>>(x, emb, out, out_size);
    loss_partial_kernel<<<256, 32>>>();
    loss_final_kernel<<<1, 32>>>(out, out_size);
}

// round 6
// speedup vs baseline: 1.0011x; 1.0011x over previous
#include <cuda_runtime.h>
#include <cuda_bf16.h>
#include <cstdint>

// ---------------- problem constants ----------------
#define N_NODES   65536
#define N_EDGES   1048576
#define KCODES    8192
#define DIM       512

#define OFF_ZQ    0
#define OFF_LOSS  33554432
#define OFF_IDX   33554433
#define OFF_EDGE  33619969

// ---------------- scratch (static device globals; no runtime alloc) ----------
__device__ __nv_bfloat16 g_xh[(size_t)N_NODES * DIM];
__device__ __nv_bfloat16 g_xl[(size_t)N_NODES * DIM];
__device__ __nv_bfloat16 g_eh[(size_t)KCODES * DIM];
__device__ __nv_bfloat16 g_el[(size_t)KCODES * DIM];
__device__ float              g_xnorm[N_NODES];
__device__ unsigned long long g_best[N_NODES];
__device__ float              g_rowsq[N_NODES];
__device__ float              g_partial[256];
__device__ int                g_edge_is64;

// ---------------- helpers ----------------
__device__ __forceinline__ uint32_t smem_u32(const void* p) {
    uint32_t a;
    asm("{ .reg .u64 t; cvta.to.shared.u64 t, %1; cvt.u32.u64 %0, t; }" : "=r"(a) : "l"(p));
    return a;
}
#define SW128(off) ((off) ^ (((off) >> 3) & 0x70))

__device__ __forceinline__ void cp16(uint32_t dst, const void* src) {
    asm volatile("cp.async.cg.shared.global [%0], [%1], 16;" :: "r"(dst), "l"(src) : "memory");
}
__device__ __forceinline__ void cp_commit() { asm volatile("cp.async.commit_group;" ::: "memory"); }
template <int N> __device__ __forceinline__ void cp_wait() {
    asm volatile("cp.async.wait_group %0;" :: "n"(N) : "memory");
}
__device__ __forceinline__ void ldsm4(uint32_t& r0, uint32_t& r1, uint32_t& r2, uint32_t& r3,
                                      uint32_t addr) {
    asm volatile("ldmatrix.sync.aligned.m8n8.x4.shared.b16 {%0,%1,%2,%3}, [%4];"
                 : "=r"(r0), "=r"(r1), "=r"(r2), "=r"(r3) : "r"(addr));
}
__device__ __forceinline__ void mma16816(float* d, const uint32_t* a, uint32_t b0, uint32_t b1) {
    asm volatile(
        "mma.sync.aligned.m16n8k16.row.col.f32.bf16.bf16.f32 "
        "{%0,%1,%2,%3},{%4,%5,%6,%7},{%8,%9},{%0,%1,%2,%3};"
        : "+f"(d[0]), "+f"(d[1]), "+f"(d[2]), "+f"(d[3])
        : "r"(a[0]), "r"(a[1]), "r"(a[2]), "r"(a[3]), "r"(b0), "r"(b1));
}
__device__ __forceinline__ unsigned f2ord(float f) {
    unsigned u = __float_as_uint(f);
    return (u & 0x80000000u) ? ~u : (u | 0x80000000u);
}
__device__ __forceinline__ unsigned long long umin64(unsigned long long a, unsigned long long b) {
    return a < b ? a : b;
}
__device__ __forceinline__ void split_bf16(float v, __nv_bfloat16& h, __nv_bfloat16& l) {
    h = __float2bfloat16_rn(v);
    l = __float2bfloat16_rn(v - __bfloat162float(h));
}

// ---------------- prep kernels ----------------
// One warp per row; XLA-GPU row-reduce order for the norm:
// lane t accumulates x[t+32j]^2 for j=0..15 sequentially (square rounded
// separately from the add), then shfl.down tree 16/8/4/2/1.
__global__ void prep_x_kernel(const float* __restrict__ x) {
    int wid = threadIdx.x >> 5;
    int lane = threadIdx.x & 31;
    int row = blockIdx.x * 8 + wid;
    const float* xr = x + (size_t)row * DIM;
    float s = 0.f;
#pragma unroll
    for (int j = 0; j < 16; j++) {
        int idx = lane + 32 * j;
        float v = xr[idx];
        s = __fadd_rn(s, __fmul_rn(v, v));          // fl(s + fl(v*v)), in order
        __nv_bfloat16 h, l;
        split_bf16(v, h, l);
        g_xh[(size_t)row * DIM + idx] = h;
        g_xl[(size_t)row * DIM + idx] = l;
    }
#pragma unroll
    for (int o = 16; o > 0; o >>= 1)
        s = __fadd_rn(s, __shfl_down_sync(0xFFFFFFFFu, s, o));
    if (lane == 0) g_xnorm[row] = s;
}

__global__ void prep_e_kernel(const float* __restrict__ emb) {
    int k = blockIdx.x;             // 8192 blocks x 128 threads
    int t = threadIdx.x;
    float4 v = ((const float4*)(emb + (size_t)k * DIM))[t];
    __nv_bfloat16 h0, h1, h2, h3, l0, l1, l2, l3;
    split_bf16(v.x, h0, l0); split_bf16(v.y, h1, l1);
    split_bf16(v.z, h2, l2); split_bf16(v.w, h3, l3);
    ((ushort4*)g_eh)[(size_t)k * (DIM / 4) + t] =
        make_ushort4(__bfloat16_as_ushort(h0), __bfloat16_as_ushort(h1),
                     __bfloat16_as_ushort(h2), __bfloat16_as_ushort(h3));
    ((ushort4*)g_el)[(size_t)k * (DIM / 4) + t] =
        make_ushort4(__bfloat16_as_ushort(l0), __bfloat16_as_ushort(l1),
                     __bfloat16_as_ushort(l2), __bfloat16_as_ushort(l3));
}

__global__ void init_best_kernel() {
    int i = blockIdx.x * blockDim.x + threadIdx.x;
    if (i < N_NODES) g_best[i] = 0xFFFFFFFFFFFFFFFFull;
}

// Detect whether edge_index arrived as raw int64 (odd 32-bit words all zero;
// node ids < 65536 so int64 upper words are 0, while int32 odd slots are
// independent nonzero values w.h.p.).
__global__ void detect_edge_kernel(const int* __restrict__ e) {
    __shared__ int any;
    if (threadIdx.x == 0) any = 0;
    __syncthreads();
    if (e[2 * threadIdx.x + 1] != 0) any = 1;
    __syncthreads();
    if (threadIdx.x == 0) g_edge_is64 = (any == 0) ? 1 : 0;
}

__global__ void edge_out_kernel(const int* __restrict__ e, float* __restrict__ out, int out_size) {
    int is64 = g_edge_is64;
    for (int i = blockIdx.x * blockDim.x + threadIdx.x; i < 2 * N_EDGES;
         i += gridDim.x * blockDim.x) {
        int o = OFF_EDGE + i;
        if (o < out_size) {
            float v = is64 ? (float)((const long long*)e)[i] : (float)e[i];
            out[o] = v;
        }
    }
}

// ---------------- main GEMM + argmin kernel (mma.sync bf16, split hi/lo) ----
#define BM 128
#define BN 128
#define BK 64
#define NCHUNK (DIM / BK)        // 8
#define T_XH 0
#define T_XL 16384
#define T_EH 32768
#define T_EL 49152
#define STAGE_BYTES 65536
#define SMEM_DYN (2 * STAGE_BYTES)   // 131072

__device__ __forceinline__ void load_chunk(uint32_t sb, int s, int kc,
                                           int m_base, int n_base, int tid) {
    uint32_t stg = sb + s * STAGE_BYTES;
#pragma unroll
    for (int t = 0; t < 16; t++) {
        int id = tid + t * 256;          // 0..4095
        int tile = id >> 10;             // 0..3 : xh, xl, eh, el
        int idx = id & 1023;
        int r = idx >> 3;
        int seg = idx & 7;
        const __nv_bfloat16* gsrc =
            (tile == 0) ? g_xh : (tile == 1) ? g_xl : (tile == 2) ? g_eh : g_el;
        int row = ((tile < 2) ? m_base : n_base) + r;
        const char* src = (const char*)gsrc + ((size_t)row * (DIM * 2) + kc * (BK * 2) + seg * 16);
        uint32_t off = (uint32_t)(r * 128 + seg * 16);
        uint32_t dst = stg + tile * 16384 + SW128(off);
        cp16(dst, src);
    }
    cp_commit();
}

__global__ void __launch_bounds__(256) vq_gemm_kernel() {
    extern __shared__ char smem[];
    uint32_t sb = smem_u32(smem);
    int tid = threadIdx.x;
    int lane = tid & 31;
    int wid = tid >> 5;
    int warp_m = wid >> 1;           // 0..3  -> 32-row band
    int warp_n = wid & 1;            // 0..1  -> 64-col band
    int m_base = blockIdx.y * BM;
    int n_base = blockIdx.x * BN;

    float acc[2][8][4];
#pragma unroll
    for (int a = 0; a < 2; a++)
#pragma unroll
        for (int b = 0; b < 8; b++)
#pragma unroll
            for (int c = 0; c < 4; c++) acc[a][b][c] = 0.f;

    load_chunk(sb, 0, 0, m_base, n_base, tid);
    load_chunk(sb, 1, 1, m_base, n_base, tid);

#pragma unroll 1
    for (int i = 0; i < NCHUNK; i++) {
        int s = i & 1;
        if (i < NCHUNK - 1) cp_wait<1>(); else cp_wait<0>();
        __syncthreads();
        uint32_t stg = sb + s * STAGE_BYTES;
#pragma unroll
        for (int kk = 0; kk < 4; kk++) {
            uint32_t axh[2][4], axl[2][4];
#pragma unroll
            for (int mt = 0; mt < 2; mt++) {
                uint32_t rowA = warp_m * 32 + mt * 16 + (lane & 15);
                uint32_t offA = SW128(rowA * 128 + kk * 32 + ((lane >> 4) << 4));
                ldsm4(axh[mt][0], axh[mt][1], axh[mt][2], axh[mt][3], stg + T_XH + offA);
                ldsm4(axl[mt][0], axl[mt][1], axl[mt][2], axl[mt][3], stg + T_XL + offA);
            }
            uint32_t bb[8][2];
#pragma unroll
            for (int jp = 0; jp < 4; jp++) {
                uint32_t rowB = warp_n * 64 + jp * 16 + (lane & 7) + ((lane >> 4) << 3);
                uint32_t offB = SW128(rowB * 128 + kk * 32 + (((lane >> 3) & 1) << 4));
                ldsm4(bb[2 * jp][0], bb[2 * jp][1], bb[2 * jp + 1][0], bb[2 * jp + 1][1],
                      stg + T_EH + offB);
            }
#pragma unroll
            for (int mt = 0; mt < 2; mt++)
#pragma unroll
                for (int j = 0; j < 8; j++) mma16816(acc[mt][j], axh[mt], bb[j][0], bb[j][1]);
#pragma unroll
            for (int mt = 0; mt < 2; mt++)
#pragma unroll
                for (int j = 0; j < 8; j++) mma16816(acc[mt][j], axl[mt], bb[j][0], bb[j][1]);
            // reload B as el, reuse axh
#pragma unroll
            for (int jp = 0; jp < 4; jp++) {
                uint32_t rowB = warp_n * 64 + jp * 16 + (lane & 7) + ((lane >> 4) << 3);
                uint32_t offB = SW128(rowB * 128 + kk * 32 + (((lane >> 3) & 1) << 4));
                ldsm4(bb[2 * jp][0], bb[2 * jp][1], bb[2 * jp + 1][0], bb[2 * jp + 1][1],
                      stg + T_EL + offB);
            }
#pragma unroll
            for (int mt = 0; mt < 2; mt++)
#pragma unroll
                for (int j = 0; j < 8; j++) mma16816(acc[mt][j], axh[mt], bb[j][0], bb[j][1]);
        }
        if (i + 2 < NCHUNK) {
            __syncthreads();
            load_chunk(sb, s, i + 2, m_base, n_base, tid);
        }
    }

    // ---- epilogue: d = fl(a - 2c) exactly as the reference rounds it ----
    // (||e_k||^2 < ULP(a)/2 always, so the reference's fl(a + b) == a: b drops out)
    int g = lane >> 2;
#pragma unroll
    for (int rr = 0; rr < 4; rr++) {
        int mt = rr >> 1, p = rr & 1;
        int row = m_base + warp_m * 32 + mt * 16 + p * 8 + g;
        float a = g_xnorm[row];
        unsigned long long best = 0xFFFFFFFFFFFFFFFFull;
#pragma unroll
        for (int j = 0; j < 8; j++) {
#pragma unroll
            for (int q = 0; q < 2; q++) {
                float c = acc[mt][j][p * 2 + q];
                float d = __fadd_rn(a, __fmul_rn(-2.0f, c));
                int col = n_base + warp_n * 64 + j * 8 + (lane & 3) * 2 + q;
                unsigned long long pk =
                    ((unsigned long long)f2ord(d) << 32) | (unsigned)col;
                best = umin64(best, pk);
            }
        }
        best = umin64(best, __shfl_xor_sync(0xFFFFFFFFu, best, 1));
        best = umin64(best, __shfl_xor_sync(0xFFFFFFFFu, best, 2));
        if ((lane & 3) == 0) atomicMin(&g_best[row], best);
    }
}

// ---------------- finalize: z_q gather (straight-through rounding), idx, sq --
__global__ void finalize_kernel(const float* __restrict__ x, const float* __restrict__ emb,
                                float* __restrict__ out, int out_size) {
    int row = blockIdx.x;           // 65536 blocks x 128 threads
    int t = threadIdx.x;
    int k = (int)(unsigned)(g_best[row] & 0xFFFFFFFFu);
    float4 ev = ((const float4*)(emb + (size_t)k * DIM))[t];
    float4 xv = ((const float4*)(x + (size_t)row * DIM))[t];
    // reference: z_q = fl(x + fl(e - x))  (double rounding, NOT exactly e)
    float4 dv;
    dv.x = __fadd_rn(ev.x, -xv.x);
    dv.y = __fadd_rn(ev.y, -xv.y);
    dv.z = __fadd_rn(ev.z, -xv.z);
    dv.w = __fadd_rn(ev.w, -xv.w);
    float4 zq;
    zq.x = __fadd_rn(xv.x, dv.x);
    zq.y = __fadd_rn(xv.y, dv.y);
    zq.z = __fadd_rn(xv.z, dv.z);
    zq.w = __fadd_rn(xv.w, dv.w);
    ((float4*)(out + OFF_ZQ))[(size_t)row * (DIM / 4) + t] = zq;
    float s = dv.x * dv.x + dv.y * dv.y + dv.z * dv.z + dv.w * dv.w;
    for (int o = 16; o > 0; o >>= 1) s += __shfl_down_sync(0xFFFFFFFFu, s, o);
    __shared__ float ws[4];
    if ((t & 31) == 0) ws[t >> 5] = s;
    __syncthreads();
    if (t == 0) {
        g_rowsq[row] = ws[0] + ws[1] + ws[2] + ws[3];
        int o = OFF_IDX + row;
        if (o < out_size) out[o] = (float)k;
    }
}

__global__ void loss_partial_kernel() {   // 256 blocks x 32 threads
    int b = blockIdx.x, t = threadIdx.x;
    float s = 0.f;
    for (int j = t; j < 256; j += 32) s += g_rowsq[b * 256 + j];
    for (int o = 16; o > 0; o >>= 1) s += __shfl_down_sync(0xFFFFFFFFu, s, o);
    if (t == 0) g_partial[b] = s;
}
__global__ void loss_final_kernel(float* __restrict__ out, int out_size) {
    if (threadIdx.x == 0 && blockIdx.x == 0) {
        float tot = 0.f;
        for (int i = 0; i < 256; i++) tot += g_partial[i];
        float loss = 1.25f * tot / (float)((size_t)N_NODES * DIM);
        if (OFF_LOSS < out_size) out[OFF_LOSS] = loss;
    }
}

// ---------------- launch ----------------
extern "C" void kernel_launch(void* const* d_in, const int* in_sizes, int n_in,
                              void* d_out, int out_size) {
    // Positional binding per metadata order: x, edge_index, emb.
    const float* x    = (const float*)d_in[0];
    const int*   eidx = (n_in > 1) ? (const int*)d_in[1] : nullptr;
    const float* emb  = (n_in > 2) ? (const float*)d_in[2] : (const float*)d_in[n_in - 1];
    // Sanity fallback: if sizes clearly identify tensors, prefer that.
    for (int i = 0; i < n_in; i++) {
        if (in_sizes[i] == N_NODES * DIM) x = (const float*)d_in[i];
        if (in_sizes[i] == KCODES * DIM && i != 0) emb = (const float*)d_in[i];
    }
    float* out = (float*)d_out;

    prep_x_kernel<<<N_NODES / 8, 256>>>(x);
    prep_e_kernel<<<KCODES, 128>>>(emb);
    init_best_kernel<<<N_NODES / 256, 256>>>();
    if (eidx) {
        detect_edge_kernel<<<1, 256>>>(eidx);
        edge_out_kernel<<<2048, 256>>>(eidx, out, out_size);
    }

    cudaFuncSetAttribute(vq_gemm_kernel, cudaFuncAttributeMaxDynamicSharedMemorySize, SMEM_DYN);
    dim3 grid(KCODES / BN, N_NODES / BM);   // (64, 512)
    vq_gemm_kernel<<<grid, 256, SMEM_DYN>>>();

    finalize_kernel<<<N_NODES, 128>>>(x, emb, out, out_size);
    loss_partial_kernel<<<256, 32>>>();
    loss_final_kernel<<<1, 32>>>(out, out_size);
}